// round 7
// baseline (speedup 1.0000x reference)
#include <cuda_runtime.h>
#include <math.h>

// Shapes fixed by the problem: T=3, B=4, N=4096, K=8.
constexpr int TT = 3;
constexpr int BB = 4;
constexpr int NN = 4096;
constexpr int KK = 8;
constexpr int CHUNKS = 2;
constexpr int CHUNK_COLS = NN / CHUNKS;    // 2048
constexpr int NPAIR = NN / 2;              // 2048 packed column pairs per set

// Partial-sum slot layout (deterministic reduction — no float atomics)
constexpr int P_CH   = 0;                  // 24 problems * 16 blocks = 384
constexpr int P_PD   = 384;                // 64
constexpr int P_SP   = 448;                // 64
constexpr int P_TRAN = 512;                // 1
constexpr int P_ARAP = 513;                // 3 * 64 = 192
constexpr int NPART  = 705;

// Scratch (device globals — no allocations allowed)
__device__ ulonglong2 g_tgtA[BB * NPAIR];      // (-2x pair, -2y pair) target
__device__ ulonglong2 g_tgtB[BB * NPAIR];      // (-2z pair, |p|^2 pair)
__device__ ulonglong2 g_dpA[TT * BB * NPAIR];  // same for deformation pts
__device__ ulonglong2 g_dpB[TT * BB * NPAIR];
__device__ float4 g_cols_src[BB * NN];         // (-2x,-2y,-2z,|x|^2) src (kNN)
__device__ float4 g_dp4[TT * BB * NN];         // raw dp coords, 16B aligned (arap)
__device__ float  g_nb_d[BB * NN * CHUNKS * KK];
__device__ int    g_nb_i[BB * NN * CHUNKS * KK];
__device__ int    g_idx[BB * NN * KK];
__device__ float  g_sd[BB * NN * KK];
__device__ float  g_partial[NPART];

// ---------------------------------------------------------------------------
__device__ __forceinline__ unsigned long long packf2(float a, float b) {
    unsigned long long r;
    asm("mov.b64 %0, {%1, %2};" : "=l"(r) : "f"(a), "f"(b));
    return r;
}
__device__ __forceinline__ void unpackf2(float& a, float& b, unsigned long long v) {
    asm("mov.b64 {%0, %1}, %2;" : "=f"(a), "=f"(b) : "l"(v));
}
__device__ __forceinline__ unsigned long long fma2(unsigned long long a,
                                                   unsigned long long b,
                                                   unsigned long long c) {
    unsigned long long d;
    asm("fma.rn.f32x2 %0, %1, %2, %3;" : "=l"(d) : "l"(a), "l"(b), "l"(c));
    return d;
}

__device__ __forceinline__ float block_reduce_sum(float v, float* sh) {
    int tid = threadIdx.x;             // blockDim.x == 256 assumed
    sh[tid] = v;
    __syncthreads();
    #pragma unroll
    for (int s = 128; s > 0; s >>= 1) {
        if (tid < s) sh[tid] += sh[tid + s];
        __syncthreads();
    }
    float r = sh[0];
    __syncthreads();
    return r;
}

__device__ __forceinline__ void insert8(float d, int n, float (&bd)[KK], int (&bi)[KK]) {
    float cd = d; int ci = n;
    #pragma unroll
    for (int s = 0; s < KK; ++s) {
        if (cd < bd[s]) {
            float td = bd[s]; int ti = bi[s];
            bd[s] = cd; bi[s] = ci;
            cd = td; ci = ti;
        }
    }
}

// ---------------------------------------------------------------------------
// Build all derived layouts:
//  - packed f32x2 column arrays for chamfer (target, dp[t])
//  - float4 column array for kNN (source)
//  - float4 raw dp coords for arap gathers
__global__ void prep_kernel(const float* __restrict__ src,
                            const float* __restrict__ tgt,
                            const float* __restrict__ dpt) {
    int i = blockIdx.x * 256 + threadIdx.x;   // 0 .. 49151
    if (i < BB * NPAIR) {                     // target pairs
        const float* p = tgt + (size_t)i * 6;
        float x0 = p[0], y0 = p[1], z0 = p[2];
        float x1 = p[3], y1 = p[4], z1 = p[5];
        float w0 = fmaf(x0, x0, fmaf(y0, y0, z0 * z0));
        float w1 = fmaf(x1, x1, fmaf(y1, y1, z1 * z1));
        g_tgtA[i] = make_ulonglong2(packf2(-2.f * x0, -2.f * x1),
                                    packf2(-2.f * y0, -2.f * y1));
        g_tgtB[i] = make_ulonglong2(packf2(-2.f * z0, -2.f * z1),
                                    packf2(w0, w1));
    } else if (i < (BB + TT * BB) * NPAIR) {  // dp pairs (+ raw dp4)
        int j = i - BB * NPAIR;
        const float* p = dpt + (size_t)j * 6;
        float x0 = p[0], y0 = p[1], z0 = p[2];
        float x1 = p[3], y1 = p[4], z1 = p[5];
        float w0 = fmaf(x0, x0, fmaf(y0, y0, z0 * z0));
        float w1 = fmaf(x1, x1, fmaf(y1, y1, z1 * z1));
        g_dpA[j] = make_ulonglong2(packf2(-2.f * x0, -2.f * x1),
                                   packf2(-2.f * y0, -2.f * y1));
        g_dpB[j] = make_ulonglong2(packf2(-2.f * z0, -2.f * z1),
                                   packf2(w0, w1));
        g_dp4[2 * j + 0] = make_float4(x0, y0, z0, 0.f);
        g_dp4[2 * j + 1] = make_float4(x1, y1, z1, 0.f);
    } else {                                  // source columns (kNN)
        int j = i - (BB + TT * BB) * NPAIR;
        if (j >= BB * NN) return;
        const float* p = src + (size_t)j * 3;
        float x = p[0], y = p[1], z = p[2];
        g_cols_src[j] = make_float4(-2.f * x, -2.f * y, -2.f * z,
                                    fmaf(x, x, fmaf(y, y, z * z)));
    }
}

// ---------------------------------------------------------------------------
// pd (sum sq diff), sp (sum abs), tran (tiny) — partial sums per block.
__global__ void small_kernel(const float* __restrict__ pw,
                             const float* __restrict__ drp,
                             const float* __restrict__ dpt,
                             const float* __restrict__ rig) {
    __shared__ float red[256];
    int g = blockIdx.x * 256 + threadIdx.x;
    float spa = 0.f, pda = 0.f;
    for (int i = g; i < TT * BB * NN; i += 64 * 256) {
        spa += fabsf(pw[i]);
        int b3 = i * 3;
        float a = drp[b3 + 0] - dpt[b3 + 0];
        float c = drp[b3 + 1] - dpt[b3 + 1];
        float e = drp[b3 + 2] - dpt[b3 + 2];
        pda += fmaf(a, a, fmaf(c, c, e * e));
    }
    float s1 = block_reduce_sum(pda, red);
    if (threadIdx.x == 0) g_partial[P_PD + blockIdx.x] = s1;
    float s2 = block_reduce_sum(spa, red);
    if (threadIdx.x == 0) g_partial[P_SP + blockIdx.x] = s2;

    float ta = 0.f;
    if (blockIdx.x == 0 && threadIdx.x < TT * BB * 3) {
        int t = threadIdx.x / 12;
        int rem = threadIdx.x % 12;
        int b = rem / 3, r = rem % 3;
        float v = rig[(((t * BB + b) * 4) + r) * 4 + 3];
        ta = v * v;
    }
    float s3 = block_reduce_sum(ta, red);
    if (blockIdx.x == 0 && threadIdx.x == 0) g_partial[P_TRAN] = s3;
}

// ---------------------------------------------------------------------------
// kNN over source points: 2 column chunks of 2048. 128-thread blocks (one row
// per thread). Relative distances (|y|^2 - 2 x.y); |x|^2 added in merge.
__global__ void __launch_bounds__(128) nb_kernel() {
    __shared__ float4 tile[CHUNK_COLS];       // 32KB
    int tid = threadIdx.x;
    int m = blockIdx.x * 128 + tid;           // 0 .. B*N-1
    int b = m >> 12;
    int ml = m & (NN - 1);
    int chunk = blockIdx.y;

    const float4* cb = g_cols_src + b * NN + chunk * CHUNK_COLS;
    for (int j = tid; j < CHUNK_COLS; j += 128) tile[j] = cb[j];
    __syncthreads();

    // row coords recovered from its own column entry: col = (-2x, ...) -> x = -0.5*col.x
    float4 me = g_cols_src[m];
    float x0 = -0.5f * me.x, x1 = -0.5f * me.y, x2 = -0.5f * me.z;

    float bd[KK]; int bi[KK];
    #pragma unroll
    for (int k = 0; k < KK; ++k) { bd[k] = 3.4e38f; bi[k] = 0; }

    int nbase = chunk * CHUNK_COLS;
    #pragma unroll 4
    for (int j = 0; j < CHUNK_COLS; ++j) {
        float4 q = tile[j];
        float d = fmaf(x2, q.z, fmaf(x1, q.y, fmaf(x0, q.x, q.w)));
        int n = nbase + j;
        if (d < bd[KK - 1] && n != ml) insert8(d, n, bd, bi);
    }

    int base = (m * CHUNKS + chunk) * KK;
    #pragma unroll
    for (int k = 0; k < KK; ++k) { g_nb_d[base + k] = bd[k]; g_nb_i[base + k] = bi[k]; }
}

// Merge the two sorted per-chunk top-8 lists. Seed with chunk 0 (sorted, zero
// inserts), then insert chunk 1 with early break (its list is sorted ascending).
__global__ void __launch_bounds__(128) nb_merge_kernel(const float* __restrict__ src) {
    int m = blockIdx.x * 128 + threadIdx.x;
    int base = m * CHUNKS * KK;
    float bd[KK]; int bi[KK];
    #pragma unroll
    for (int k = 0; k < KK; ++k) { bd[k] = g_nb_d[base + k]; bi[k] = g_nb_i[base + k]; }
    #pragma unroll
    for (int c = KK; c < 2 * KK; ++c) {
        float d = g_nb_d[base + c];
        if (d >= bd[KK - 1]) break;      // both lists sorted; no later one can fit
        insert8(d, g_nb_i[base + c], bd, bi);
    }
    const float* rp = src + (size_t)m * 3;
    float x0 = rp[0], x1 = rp[1], x2 = rp[2];
    float x2m = fmaf(x0, x0, fmaf(x1, x1, x2 * x2));
    #pragma unroll
    for (int k = 0; k < KK; ++k) {
        g_idx[m * KK + k] = bi[k];
        g_sd[m * KK + k]  = sqrtf(bd[k] + x2m + 1e-5f);
    }
}

// ---------------------------------------------------------------------------
// Chamfer: 24 problems = (t, b, dir). Columns pre-packed in f32x2 pairs.
// Inner loop per 2 columns: 2 LDS.128 + 3 FFMA2 + 2 FMNMX.
__global__ void chamfer_kernel(const float* __restrict__ dpt,
                               const float* __restrict__ tgt) {
    __shared__ ulonglong2 tA[512];     // 8KB — 1024 columns per tile
    __shared__ ulonglong2 tB[512];     // 8KB
    __shared__ float red[256];
    int tid = threadIdx.x;
    int p = blockIdx.y;                // ((t*BB + b)*2 + dir)
    int dir = p & 1;
    int tb = p >> 1;
    int b = tb & 3;

    const float* rowp;
    const ulonglong2 *cA, *cB;
    if (dir == 0) { rowp = dpt + (size_t)tb * NN * 3; cA = g_tgtA + b * NPAIR;  cB = g_tgtB + b * NPAIR; }
    else          { rowp = tgt + (size_t)b * NN * 3;  cA = g_dpA + tb * NPAIR;  cB = g_dpB + tb * NPAIR; }

    int m = blockIdx.x * 256 + tid;
    const float* rp = rowp + (size_t)m * 3;
    float x0 = rp[0], x1 = rp[1], x2 = rp[2];
    float x2m = fmaf(x0, x0, fmaf(x1, x1, x2 * x2));
    unsigned long long X0 = packf2(x0, x0);
    unsigned long long X1 = packf2(x1, x1);
    unsigned long long X2 = packf2(x2, x2);

    float r0 = 3.4e38f, r1 = 3.4e38f;
    for (int t0 = 0; t0 < NPAIR; t0 += 512) {
        __syncthreads();
        for (int j = tid; j < 512; j += 256) { tA[j] = cA[t0 + j]; tB[j] = cB[t0 + j]; }
        __syncthreads();
        #pragma unroll 16
        for (int j = 0; j < 512; ++j) {
            ulonglong2 a = tA[j];
            ulonglong2 bb = tB[j];
            unsigned long long d = fma2(X2, bb.x, bb.y);
            d = fma2(X1, a.y, d);
            d = fma2(X0, a.x, d);
            float lo, hi;
            unpackf2(lo, hi, d);
            r0 = fminf(r0, lo);
            r1 = fminf(r1, hi);
        }
    }
    float v = fminf(r0, r1) + x2m;
    float s = block_reduce_sum(v, red);
    if (tid == 0) g_partial[P_CH + p * 16 + blockIdx.x] = s;
}

// ---------------------------------------------------------------------------
// ARAP per t: gather dp neighbors (float4, 1 LDG.128 each), compare to source
// distances precomputed in nb_merge.
__global__ void arap_kernel() {
    __shared__ float red[256];
    int t = blockIdx.y;
    int i = blockIdx.x * 256 + threadIdx.x;    // b*NN + n
    int b = i >> 12;
    const float4* dpb = g_dp4 + (size_t)(t * BB + b) * NN;
    float4 pme = dpb[i & (NN - 1)];
    float acc = 0.f;
    #pragma unroll
    for (int k = 0; k < KK; ++k) {
        int j = g_idx[i * KK + k];
        float4 q = dpb[j];
        float dx = q.x - pme.x;
        float dy = q.y - pme.y;
        float dz = q.z - pme.z;
        float dd = sqrtf(fmaf(dx, dx, fmaf(dy, dy, dz * dz)) + 1e-5f);
        float df = dd - g_sd[i * KK + k];
        acc = fmaf(df, df, acc);
    }
    float s = block_reduce_sum(acc, red);
    if (threadIdx.x == 0) g_partial[P_ARAP + t * 64 + blockIdx.x] = s;
}

// ---------------------------------------------------------------------------
// Final deterministic weighted reduction of all partial slots.
__global__ void final_kernel(float* __restrict__ out) {
    __shared__ float red[256];
    int tid = threadIdx.x;
    float acc = 0.f;
    for (int s = tid; s < NPART; s += 256) {
        float w;
        if (s < P_PD)        w = 0.5f / BB;          // chamfer: *0.5/B
        else if (s < P_SP)   w = 1.0f / BB;          // pd: /B
        else if (s < P_TRAN) w = 1.0f / (BB * NN);   // sp: mean over B*N
        else                 w = 1.0f / BB;          // tran + arap: /B
        acc += w * g_partial[s];
    }
    float s = block_reduce_sum(acc, red);
    if (tid == 0) out[0] = s;
}

// ---------------------------------------------------------------------------
extern "C" void kernel_launch(void* const* d_in, const int* in_sizes, int n_in,
                              void* d_out, int out_size) {
    (void)in_sizes; (void)n_in; (void)out_size;
    const float* pw  = (const float*)d_in[1];  // point_weight [T,B,N,1]
    const float* drp = (const float*)d_in[2];  // deform_rigid_points [T,B,N,3]
    const float* dpt = (const float*)d_in[3];  // deformation_points [T,B,N,3]
    const float* rig = (const float*)d_in[4];  // rigid_matrix [T,B,4,4]
    const float* src = (const float*)d_in[5];  // source_points [B,N,3]
    const float* tgt = (const float*)d_in[6];  // target_points [B,N,3]

    prep_kernel<<<192, 256>>>(src, tgt, dpt);
    small_kernel<<<64, 256>>>(pw, drp, dpt, rig);
    nb_kernel<<<dim3(BB * NN / 128, CHUNKS), 128>>>();
    nb_merge_kernel<<<BB * NN / 128, 128>>>(src);
    chamfer_kernel<<<dim3(16, 24), 256>>>(dpt, tgt);
    arap_kernel<<<dim3(BB * NN / 256, TT), 256>>>();
    final_kernel<<<1, 256>>>((float*)d_out);
}

// round 8
// speedup vs baseline: 1.2203x; 1.2203x over previous
#include <cuda_runtime.h>
#include <math.h>

// Shapes fixed by the problem: T=3, B=4, N=4096, K=8.
constexpr int TT = 3;
constexpr int BB = 4;
constexpr int NN = 4096;
constexpr int KK = 8;
constexpr int TOT = BB * NN;               // 16384 rows
constexpr int CHUNKS = 4;
constexpr int CHUNK_COLS = NN / CHUNKS;    // 1024
constexpr int NPAIR = NN / 2;              // 2048 packed column pairs per set

// Partial-sum slot layout (deterministic reduction — no float atomics)
constexpr int P_CH   = 0;                  // 24 problems * 16 blocks = 384
constexpr int P_PD   = 384;                // 64
constexpr int P_SP   = 448;                // 64
constexpr int P_TRAN = 512;                // 1
constexpr int P_ARAP = 513;                // 3 * 64 = 192
constexpr int NPART  = 705;

// Scratch (device globals — no allocations allowed)
__device__ ulonglong2 g_tgtA[BB * NPAIR];      // (-2x pair, -2y pair) target
__device__ ulonglong2 g_tgtB[BB * NPAIR];      // (-2z pair, |p|^2 pair)
__device__ ulonglong2 g_dpA[TT * BB * NPAIR];  // same for deformation pts
__device__ ulonglong2 g_dpB[TT * BB * NPAIR];
__device__ float4 g_cols_src[TOT];             // (-2x,-2y,-2z,|x|^2) src (kNN)
__device__ float4 g_dp4[TT * TOT];             // raw dp coords (arap gathers)
__device__ float  g_nb_d[CHUNKS * KK * TOT];   // [chunk][k][m] — coalesced
__device__ int    g_nb_i[CHUNKS * KK * TOT];
__device__ int    g_idx[KK * TOT];             // [k][m]
__device__ float  g_sd[KK * TOT];
__device__ float  g_partial[NPART];

// ---------------------------------------------------------------------------
__device__ __forceinline__ unsigned long long packf2(float a, float b) {
    unsigned long long r;
    asm("mov.b64 %0, {%1, %2};" : "=l"(r) : "f"(a), "f"(b));
    return r;
}
__device__ __forceinline__ void unpackf2(float& a, float& b, unsigned long long v) {
    asm("mov.b64 {%0, %1}, %2;" : "=f"(a), "=f"(b) : "l"(v));
}
__device__ __forceinline__ unsigned long long fma2(unsigned long long a,
                                                   unsigned long long b,
                                                   unsigned long long c) {
    unsigned long long d;
    asm("fma.rn.f32x2 %0, %1, %2, %3;" : "=l"(d) : "l"(a), "l"(b), "l"(c));
    return d;
}

template <int BS>
__device__ __forceinline__ float block_reduce_sum(float v, float* sh) {
    int tid = threadIdx.x;
    sh[tid] = v;
    __syncthreads();
    #pragma unroll
    for (int s = BS / 2; s > 0; s >>= 1) {
        if (tid < s) sh[tid] += sh[tid + s];
        __syncthreads();
    }
    float r = sh[0];
    __syncthreads();
    return r;
}

__device__ __forceinline__ void insert8(float d, int n, float (&bd)[KK], int (&bi)[KK]) {
    float cd = d; int ci = n;
    #pragma unroll
    for (int s = 0; s < KK; ++s) {
        if (cd < bd[s]) {
            float td = bd[s]; int ti = bi[s];
            bd[s] = cd; bi[s] = ci;
            cd = td; ci = ti;
        }
    }
}

// ---------------------------------------------------------------------------
// Build all derived layouts.
__global__ void prep_kernel(const float* __restrict__ src,
                            const float* __restrict__ tgt,
                            const float* __restrict__ dpt) {
    int i = blockIdx.x * 256 + threadIdx.x;   // 0 .. 49151
    if (i < BB * NPAIR) {                     // target pairs
        const float* p = tgt + (size_t)i * 6;
        float x0 = p[0], y0 = p[1], z0 = p[2];
        float x1 = p[3], y1 = p[4], z1 = p[5];
        float w0 = fmaf(x0, x0, fmaf(y0, y0, z0 * z0));
        float w1 = fmaf(x1, x1, fmaf(y1, y1, z1 * z1));
        g_tgtA[i] = make_ulonglong2(packf2(-2.f * x0, -2.f * x1),
                                    packf2(-2.f * y0, -2.f * y1));
        g_tgtB[i] = make_ulonglong2(packf2(-2.f * z0, -2.f * z1),
                                    packf2(w0, w1));
    } else if (i < (BB + TT * BB) * NPAIR) {  // dp pairs (+ raw dp4)
        int j = i - BB * NPAIR;
        const float* p = dpt + (size_t)j * 6;
        float x0 = p[0], y0 = p[1], z0 = p[2];
        float x1 = p[3], y1 = p[4], z1 = p[5];
        float w0 = fmaf(x0, x0, fmaf(y0, y0, z0 * z0));
        float w1 = fmaf(x1, x1, fmaf(y1, y1, z1 * z1));
        g_dpA[j] = make_ulonglong2(packf2(-2.f * x0, -2.f * x1),
                                   packf2(-2.f * y0, -2.f * y1));
        g_dpB[j] = make_ulonglong2(packf2(-2.f * z0, -2.f * z1),
                                   packf2(w0, w1));
        g_dp4[2 * j + 0] = make_float4(x0, y0, z0, 0.f);
        g_dp4[2 * j + 1] = make_float4(x1, y1, z1, 0.f);
    } else {                                  // source columns (kNN)
        int j = i - (BB + TT * BB) * NPAIR;
        if (j >= TOT) return;
        const float* p = src + (size_t)j * 3;
        float x = p[0], y = p[1], z = p[2];
        g_cols_src[j] = make_float4(-2.f * x, -2.f * y, -2.f * z,
                                    fmaf(x, x, fmaf(y, y, z * z)));
    }
}

// ---------------------------------------------------------------------------
// pd (sum sq diff), sp (sum abs), tran (tiny) — partial sums per block.
__global__ void small_kernel(const float* __restrict__ pw,
                             const float* __restrict__ drp,
                             const float* __restrict__ dpt,
                             const float* __restrict__ rig) {
    __shared__ float red[256];
    int g = blockIdx.x * 256 + threadIdx.x;
    float spa = 0.f, pda = 0.f;
    for (int i = g; i < TT * TOT; i += 64 * 256) {
        spa += fabsf(pw[i]);
        int b3 = i * 3;
        float a = drp[b3 + 0] - dpt[b3 + 0];
        float c = drp[b3 + 1] - dpt[b3 + 1];
        float e = drp[b3 + 2] - dpt[b3 + 2];
        pda += fmaf(a, a, fmaf(c, c, e * e));
    }
    float s1 = block_reduce_sum<256>(pda, red);
    if (threadIdx.x == 0) g_partial[P_PD + blockIdx.x] = s1;
    float s2 = block_reduce_sum<256>(spa, red);
    if (threadIdx.x == 0) g_partial[P_SP + blockIdx.x] = s2;

    float ta = 0.f;
    if (blockIdx.x == 0 && threadIdx.x < TT * BB * 3) {
        int t = threadIdx.x / 12;
        int rem = threadIdx.x % 12;
        int b = rem / 3, r = rem % 3;
        float v = rig[(((t * BB + b) * 4) + r) * 4 + 3];
        ta = v * v;
    }
    float s3 = block_reduce_sum<256>(ta, red);
    if (blockIdx.x == 0 && threadIdx.x == 0) g_partial[P_TRAN] = s3;
}

// ---------------------------------------------------------------------------
// kNN over source points: 4 column chunks of 1024, 256-thread blocks
// (one row per thread). Relative distances; |x|^2 added in merge.
// Outputs transposed [chunk][k][m] for coalesced merge reads.
__global__ void __launch_bounds__(256) nb_kernel() {
    __shared__ float4 tile[CHUNK_COLS];       // 16KB
    int tid = threadIdx.x;
    int m = blockIdx.x * 256 + tid;           // 0 .. TOT-1
    int b = m >> 12;
    int ml = m & (NN - 1);
    int chunk = blockIdx.y;

    const float4* cb = g_cols_src + b * NN + chunk * CHUNK_COLS;
    for (int j = tid; j < CHUNK_COLS; j += 256) tile[j] = cb[j];
    __syncthreads();

    float4 me = g_cols_src[m];   // (-2x,...) -> x = -0.5 * .x
    float x0 = -0.5f * me.x, x1 = -0.5f * me.y, x2 = -0.5f * me.z;

    float bd[KK]; int bi[KK];
    #pragma unroll
    for (int k = 0; k < KK; ++k) { bd[k] = 3.4e38f; bi[k] = 0; }

    int nbase = chunk * CHUNK_COLS;
    #pragma unroll 4
    for (int j = 0; j < CHUNK_COLS; ++j) {
        float4 q = tile[j];
        float d = fmaf(x2, q.z, fmaf(x1, q.y, fmaf(x0, q.x, q.w)));
        int n = nbase + j;
        if (d < bd[KK - 1] && n != ml) insert8(d, n, bd, bi);
    }

    #pragma unroll
    for (int k = 0; k < KK; ++k) {
        g_nb_d[(chunk * KK + k) * TOT + m] = bd[k];
        g_nb_i[(chunk * KK + k) * TOT + m] = bi[k];
    }
}

// Merge the 4 sorted per-chunk top-8 lists (all reads coalesced over m).
__global__ void __launch_bounds__(256) nb_merge_kernel(const float* __restrict__ src) {
    int m = blockIdx.x * 256 + threadIdx.x;
    float bd[KK]; int bi[KK];
    #pragma unroll
    for (int k = 0; k < KK; ++k) {            // seed with chunk 0 (sorted)
        bd[k] = g_nb_d[k * TOT + m];
        bi[k] = g_nb_i[k * TOT + m];
    }
    for (int c = 1; c < CHUNKS; ++c) {
        #pragma unroll
        for (int k = 0; k < KK; ++k) {
            float d = g_nb_d[(c * KK + k) * TOT + m];
            if (d >= bd[KK - 1]) break;       // sorted list — no later fit
            insert8(d, g_nb_i[(c * KK + k) * TOT + m], bd, bi);
        }
    }
    const float* rp = src + (size_t)m * 3;
    float x0 = rp[0], x1 = rp[1], x2 = rp[2];
    float x2m = fmaf(x0, x0, fmaf(x1, x1, x2 * x2));
    #pragma unroll
    for (int k = 0; k < KK; ++k) {
        g_idx[k * TOT + m] = bi[k];
        g_sd[k * TOT + m]  = sqrtf(bd[k] + x2m + 1e-5f);
    }
}

// ---------------------------------------------------------------------------
// Chamfer: 24 problems = (t, b, dir); 2-row register tiling + f32x2 columns.
// Per 2 columns per thread: 2 LDS.128 + 2 rows x (3 FFMA2 + 2 FMNMX).
__global__ void __launch_bounds__(128) chamfer_kernel(const float* __restrict__ dpt,
                                                      const float* __restrict__ tgt) {
    __shared__ ulonglong2 tA[512];     // 8KB — 1024 columns per tile
    __shared__ ulonglong2 tB[512];     // 8KB
    __shared__ float red[128];
    int tid = threadIdx.x;
    int p = blockIdx.y;                // ((t*BB + b)*2 + dir)
    int dir = p & 1;
    int tb = p >> 1;
    int b = tb & 3;

    const float* rowp;
    const ulonglong2 *cA, *cB;
    if (dir == 0) { rowp = dpt + (size_t)tb * NN * 3; cA = g_tgtA + b * NPAIR;  cB = g_tgtB + b * NPAIR; }
    else          { rowp = tgt + (size_t)b * NN * 3;  cA = g_dpA + tb * NPAIR;  cB = g_dpB + tb * NPAIR; }

    int m0 = blockIdx.x * 256 + tid;   // rows m0 and m0+128
    const float* rp0 = rowp + (size_t)m0 * 3;
    const float* rp1 = rp0 + 128 * 3;
    float a0 = rp0[0], a1 = rp0[1], a2 = rp0[2];
    float b0 = rp1[0], b1 = rp1[1], b2 = rp1[2];
    float x2m0 = fmaf(a0, a0, fmaf(a1, a1, a2 * a2));
    float x2m1 = fmaf(b0, b0, fmaf(b1, b1, b2 * b2));
    unsigned long long XA0 = packf2(a0, a0), XA1 = packf2(a1, a1), XA2 = packf2(a2, a2);
    unsigned long long XB0 = packf2(b0, b0), XB1 = packf2(b1, b1), XB2 = packf2(b2, b2);

    float r0lo = 3.4e38f, r0hi = 3.4e38f, r1lo = 3.4e38f, r1hi = 3.4e38f;
    for (int t0 = 0; t0 < NPAIR; t0 += 512) {
        __syncthreads();
        #pragma unroll
        for (int j = tid; j < 512; j += 128) { tA[j] = cA[t0 + j]; tB[j] = cB[t0 + j]; }
        __syncthreads();
        #pragma unroll 8
        for (int j = 0; j < 512; ++j) {
            ulonglong2 ca = tA[j];
            ulonglong2 cb = tB[j];
            unsigned long long d0 = fma2(XA2, cb.x, cb.y);
            unsigned long long d1 = fma2(XB2, cb.x, cb.y);
            d0 = fma2(XA1, ca.y, d0);
            d1 = fma2(XB1, ca.y, d1);
            d0 = fma2(XA0, ca.x, d0);
            d1 = fma2(XB0, ca.x, d1);
            float lo, hi;
            unpackf2(lo, hi, d0);
            r0lo = fminf(r0lo, lo); r0hi = fminf(r0hi, hi);
            unpackf2(lo, hi, d1);
            r1lo = fminf(r1lo, lo); r1hi = fminf(r1hi, hi);
        }
    }
    float v = (fminf(r0lo, r0hi) + x2m0) + (fminf(r1lo, r1hi) + x2m1);
    float s = block_reduce_sum<128>(v, red);
    if (tid == 0) g_partial[P_CH + p * 16 + blockIdx.x] = s;
}

// ---------------------------------------------------------------------------
// ARAP per t: gather dp neighbors (float4 LDG.128), compare to source dists.
__global__ void arap_kernel() {
    __shared__ float red[256];
    int t = blockIdx.y;
    int i = blockIdx.x * 256 + threadIdx.x;    // b*NN + n
    int b = i >> 12;
    const float4* dpb = g_dp4 + (size_t)(t * BB + b) * NN;
    float4 pme = dpb[i & (NN - 1)];
    float acc = 0.f;
    #pragma unroll
    for (int k = 0; k < KK; ++k) {
        int j = g_idx[k * TOT + i];
        float4 q = dpb[j];
        float dx = q.x - pme.x;
        float dy = q.y - pme.y;
        float dz = q.z - pme.z;
        float dd = sqrtf(fmaf(dx, dx, fmaf(dy, dy, dz * dz)) + 1e-5f);
        float df = dd - g_sd[k * TOT + i];
        acc = fmaf(df, df, acc);
    }
    float s = block_reduce_sum<256>(acc, red);
    if (threadIdx.x == 0) g_partial[P_ARAP + t * 64 + blockIdx.x] = s;
}

// ---------------------------------------------------------------------------
// Final deterministic weighted reduction of all partial slots.
__global__ void final_kernel(float* __restrict__ out) {
    __shared__ float red[256];
    int tid = threadIdx.x;
    float acc = 0.f;
    for (int s = tid; s < NPART; s += 256) {
        float w;
        if (s < P_PD)        w = 0.5f / BB;          // chamfer: *0.5/B
        else if (s < P_SP)   w = 1.0f / BB;          // pd: /B
        else if (s < P_TRAN) w = 1.0f / (BB * NN);   // sp: mean over B*N
        else                 w = 1.0f / BB;          // tran + arap: /B
        acc += w * g_partial[s];
    }
    float s = block_reduce_sum<256>(acc, red);
    if (tid == 0) out[0] = s;
}

// ---------------------------------------------------------------------------
extern "C" void kernel_launch(void* const* d_in, const int* in_sizes, int n_in,
                              void* d_out, int out_size) {
    (void)in_sizes; (void)n_in; (void)out_size;
    const float* pw  = (const float*)d_in[1];  // point_weight [T,B,N,1]
    const float* drp = (const float*)d_in[2];  // deform_rigid_points [T,B,N,3]
    const float* dpt = (const float*)d_in[3];  // deformation_points [T,B,N,3]
    const float* rig = (const float*)d_in[4];  // rigid_matrix [T,B,4,4]
    const float* src = (const float*)d_in[5];  // source_points [B,N,3]
    const float* tgt = (const float*)d_in[6];  // target_points [B,N,3]

    prep_kernel<<<192, 256>>>(src, tgt, dpt);
    small_kernel<<<64, 256>>>(pw, drp, dpt, rig);
    nb_kernel<<<dim3(TOT / 256, CHUNKS), 256>>>();
    chamfer_kernel<<<dim3(16, 24), 128>>>(dpt, tgt);   // 4th launch — ncu target
    nb_merge_kernel<<<TOT / 256, 256>>>(src);
    arap_kernel<<<dim3(TOT / 256, TT), 256>>>();
    final_kernel<<<1, 256>>>((float*)d_out);
}

// round 9
// speedup vs baseline: 1.4478x; 1.1865x over previous
#include <cuda_runtime.h>
#include <math.h>

// Shapes fixed by the problem: T=3, B=4, N=4096, K=8.
constexpr int TT = 3;
constexpr int BB = 4;
constexpr int NN = 4096;
constexpr int KK = 8;
constexpr int TOT = BB * NN;               // 16384 rows
constexpr int NB_CHUNKS = 8;
constexpr int NB_COLS = NN / NB_CHUNKS;    // 512
constexpr int NB_K = 9;                    // top-9 (self dropped in merge)
constexpr int NPAIR = NN / 2;              // 2048 packed column pairs per set
constexpr int CCH = 4;                     // chamfer column chunks
constexpr int CPAIR = NPAIR / CCH;         // 512 pairs per chamfer chunk

// Partial-sum slot layout (deterministic reduction — no float atomics)
constexpr int P_CH   = 0;                  // 24 problems * 16 blocks = 384
constexpr int P_PD   = 384;                // 64
constexpr int P_SP   = 448;                // 64
constexpr int P_TRAN = 512;                // 1
constexpr int P_ARAP = 513;                // 3 * 64 = 192
constexpr int NPART  = 705;

// Scratch (device globals — no allocations allowed)
__device__ ulonglong2 g_tgtA[BB * NPAIR];      // (-2x pair, -2y pair) target
__device__ ulonglong2 g_tgtB[BB * NPAIR];      // (-2z pair, |p|^2 pair)
__device__ ulonglong2 g_dpA[TT * BB * NPAIR];  // same for deformation pts
__device__ ulonglong2 g_dpB[TT * BB * NPAIR];
__device__ float4 g_cols_src[TOT];             // (-2x,-2y,-2z,|x|^2) src (kNN)
__device__ float4 g_dp4[TT * TOT];             // raw dp coords (arap gathers)
__device__ unsigned int g_nb[NB_CHUNKS * NB_K * TOT];  // packed keys [chunk][k][m]
__device__ int    g_idx[KK * TOT];             // [k][m]
__device__ float  g_sd[KK * TOT];
__device__ float  g_cmin[24 * CCH * NN];       // chamfer partial row-mins
__device__ float  g_partial[NPART];

// ---------------------------------------------------------------------------
__device__ __forceinline__ unsigned long long packf2(float a, float b) {
    unsigned long long r;
    asm("mov.b64 %0, {%1, %2};" : "=l"(r) : "f"(a), "f"(b));
    return r;
}
__device__ __forceinline__ void unpackf2(float& a, float& b, unsigned long long v) {
    asm("mov.b64 {%0, %1}, %2;" : "=f"(a), "=f"(b) : "l"(v));
}
__device__ __forceinline__ unsigned long long fma2(unsigned long long a,
                                                   unsigned long long b,
                                                   unsigned long long c) {
    unsigned long long d;
    asm("fma.rn.f32x2 %0, %1, %2, %3;" : "=l"(d) : "l"(a), "l"(b), "l"(c));
    return d;
}

template <int BS>
__device__ __forceinline__ float block_reduce_sum(float v, float* sh) {
    int tid = threadIdx.x;
    sh[tid] = v;
    __syncthreads();
    #pragma unroll
    for (int s = BS / 2; s > 0; s >>= 1) {
        if (tid < s) sh[tid] += sh[tid + s];
        __syncthreads();
    }
    float r = sh[0];
    __syncthreads();
    return r;
}

// ---------------------------------------------------------------------------
// Build all derived layouts.
__global__ void prep_kernel(const float* __restrict__ src,
                            const float* __restrict__ tgt,
                            const float* __restrict__ dpt) {
    int i = blockIdx.x * 256 + threadIdx.x;   // 0 .. 49151
    if (i < BB * NPAIR) {                     // target pairs
        const float* p = tgt + (size_t)i * 6;
        float x0 = p[0], y0 = p[1], z0 = p[2];
        float x1 = p[3], y1 = p[4], z1 = p[5];
        float w0 = fmaf(x0, x0, fmaf(y0, y0, z0 * z0));
        float w1 = fmaf(x1, x1, fmaf(y1, y1, z1 * z1));
        g_tgtA[i] = make_ulonglong2(packf2(-2.f * x0, -2.f * x1),
                                    packf2(-2.f * y0, -2.f * y1));
        g_tgtB[i] = make_ulonglong2(packf2(-2.f * z0, -2.f * z1),
                                    packf2(w0, w1));
    } else if (i < (BB + TT * BB) * NPAIR) {  // dp pairs (+ raw dp4)
        int j = i - BB * NPAIR;
        const float* p = dpt + (size_t)j * 6;
        float x0 = p[0], y0 = p[1], z0 = p[2];
        float x1 = p[3], y1 = p[4], z1 = p[5];
        float w0 = fmaf(x0, x0, fmaf(y0, y0, z0 * z0));
        float w1 = fmaf(x1, x1, fmaf(y1, y1, z1 * z1));
        g_dpA[j] = make_ulonglong2(packf2(-2.f * x0, -2.f * x1),
                                   packf2(-2.f * y0, -2.f * y1));
        g_dpB[j] = make_ulonglong2(packf2(-2.f * z0, -2.f * z1),
                                   packf2(w0, w1));
        g_dp4[2 * j + 0] = make_float4(x0, y0, z0, 0.f);
        g_dp4[2 * j + 1] = make_float4(x1, y1, z1, 0.f);
    } else {                                  // source columns (kNN)
        int j = i - (BB + TT * BB) * NPAIR;
        if (j >= TOT) return;
        const float* p = src + (size_t)j * 3;
        float x = p[0], y = p[1], z = p[2];
        g_cols_src[j] = make_float4(-2.f * x, -2.f * y, -2.f * z,
                                    fmaf(x, x, fmaf(y, y, z * z)));
    }
}

// ---------------------------------------------------------------------------
// pd (sum sq diff), sp (sum abs), tran (tiny) — partial sums per block.
__global__ void small_kernel(const float* __restrict__ pw,
                             const float* __restrict__ drp,
                             const float* __restrict__ dpt,
                             const float* __restrict__ rig) {
    __shared__ float red[256];
    int g = blockIdx.x * 256 + threadIdx.x;
    float spa = 0.f, pda = 0.f;
    for (int i = g; i < TT * TOT; i += 64 * 256) {
        spa += fabsf(pw[i]);
        int b3 = i * 3;
        float a = drp[b3 + 0] - dpt[b3 + 0];
        float c = drp[b3 + 1] - dpt[b3 + 1];
        float e = drp[b3 + 2] - dpt[b3 + 2];
        pda += fmaf(a, a, fmaf(c, c, e * e));
    }
    float s1 = block_reduce_sum<256>(pda, red);
    if (threadIdx.x == 0) g_partial[P_PD + blockIdx.x] = s1;
    float s2 = block_reduce_sum<256>(spa, red);
    if (threadIdx.x == 0) g_partial[P_SP + blockIdx.x] = s2;

    float ta = 0.f;
    if (blockIdx.x == 0 && threadIdx.x < TT * BB * 3) {
        int t = threadIdx.x / 12;
        int rem = threadIdx.x % 12;
        int b = rem / 3, r = rem % 3;
        float v = rig[(((t * BB + b) * 4) + r) * 4 + 3];
        ta = v * v;
    }
    float s3 = block_reduce_sum<256>(ta, red);
    if (blockIdx.x == 0 && threadIdx.x == 0) g_partial[P_TRAN] = s3;
}

// ---------------------------------------------------------------------------
// Chamfer pass 1: 24 problems x 4 column chunks; 4-row register tiling +
// f32x2 packed columns. Writes per-row RELATIVE min (no |x|^2) per chunk.
__global__ void __launch_bounds__(128) chamfer_kernel(const float* __restrict__ dpt,
                                                      const float* __restrict__ tgt) {
    __shared__ ulonglong2 tA[CPAIR];   // 8KB — 1024 columns
    __shared__ ulonglong2 tB[CPAIR];   // 8KB
    int tid = threadIdx.x;
    int by = blockIdx.y;               // p*CCH + cc
    int p = by >> 2;                   // ((t*BB + b)*2 + dir)
    int cc = by & 3;
    int dir = p & 1;
    int tb = p >> 1;
    int b = tb & 3;

    const float* rowp;
    const ulonglong2 *cA, *cB;
    if (dir == 0) { rowp = dpt + (size_t)tb * NN * 3; cA = g_tgtA + b * NPAIR;  cB = g_tgtB + b * NPAIR; }
    else          { rowp = tgt + (size_t)b * NN * 3;  cA = g_dpA + tb * NPAIR;  cB = g_dpB + tb * NPAIR; }
    cA += cc * CPAIR;
    cB += cc * CPAIR;

    #pragma unroll
    for (int j = tid; j < CPAIR; j += 128) { tA[j] = cA[j]; tB[j] = cB[j]; }
    __syncthreads();

    int m0 = blockIdx.x * 512 + tid;   // rows m0, +128, +256, +384
    unsigned long long X0[4], X1[4], X2[4];
    #pragma unroll
    for (int r = 0; r < 4; ++r) {
        const float* rp = rowp + (size_t)(m0 + r * 128) * 3;
        float a0 = rp[0], a1 = rp[1], a2 = rp[2];
        X0[r] = packf2(a0, a0); X1[r] = packf2(a1, a1); X2[r] = packf2(a2, a2);
    }

    float rlo[4], rhi[4];
    #pragma unroll
    for (int r = 0; r < 4; ++r) { rlo[r] = 3.4e38f; rhi[r] = 3.4e38f; }

    #pragma unroll 4
    for (int j = 0; j < CPAIR; ++j) {
        ulonglong2 ca = tA[j];
        ulonglong2 cb = tB[j];
        #pragma unroll
        for (int r = 0; r < 4; ++r) {
            unsigned long long d = fma2(X2[r], cb.x, cb.y);
            d = fma2(X1[r], ca.y, d);
            d = fma2(X0[r], ca.x, d);
            float lo, hi;
            unpackf2(lo, hi, d);
            rlo[r] = fminf(rlo[r], lo);
            rhi[r] = fminf(rhi[r], hi);
        }
    }
    float* out = g_cmin + (size_t)by * NN;
    #pragma unroll
    for (int r = 0; r < 4; ++r)
        out[m0 + r * 128] = fminf(rlo[r], rhi[r]);
}

// Chamfer pass 2: combine 4 chunk mins + |x|^2, block-sum into partials.
__global__ void __launch_bounds__(256) chamfer_combine(const float* __restrict__ dpt,
                                                       const float* __restrict__ tgt) {
    __shared__ float red[256];
    int p = blockIdx.y;
    int dir = p & 1;
    int tb = p >> 1;
    int b = tb & 3;
    const float* rowp = (dir == 0) ? dpt + (size_t)tb * NN * 3
                                   : tgt + (size_t)b * NN * 3;
    int m = blockIdx.x * 256 + threadIdx.x;
    const float* cm = g_cmin + (size_t)p * CCH * NN + m;
    float v = fminf(fminf(cm[0], cm[NN]), fminf(cm[2 * NN], cm[3 * NN]));
    const float* rp = rowp + (size_t)m * 3;
    float x0 = rp[0], x1 = rp[1], x2 = rp[2];
    v += fmaf(x0, x0, fmaf(x1, x1, x2 * x2));
    float s = block_reduce_sum<256>(v, red);
    if (threadIdx.x == 0) g_partial[P_CH + p * 16 + blockIdx.x] = s;
}

// ---------------------------------------------------------------------------
// kNN pass 1: 8 column chunks of 512; one row per thread. Branchless
// packed-key top-9 ladder: key = (bits(d_true) & ~0xFFF) | colIdx.
// d_true >= 0 so float bits are order-monotone; IMNMX runs on the alu pipe.
__global__ void __launch_bounds__(256) nb_kernel() {
    __shared__ float4 tile[NB_COLS];          // 8KB
    int tid = threadIdx.x;
    int m = blockIdx.x * 256 + tid;           // 0 .. TOT-1
    int b = m >> 12;
    int chunk = blockIdx.y;

    const float4* cb = g_cols_src + b * NN + chunk * NB_COLS;
    #pragma unroll
    for (int j = tid; j < NB_COLS; j += 256) tile[j] = cb[j];
    __syncthreads();

    float4 me = g_cols_src[m];   // (-2x,-2y,-2z,|x|^2)
    float x0 = -0.5f * me.x, x1 = -0.5f * me.y, x2 = -0.5f * me.z;
    float x2m = me.w;

    unsigned int bd[NB_K];
    #pragma unroll
    for (int k = 0; k < NB_K; ++k) bd[k] = 0xFFFFFFFFu;

    unsigned int nbase = chunk * NB_COLS;
    #pragma unroll 4
    for (int j = 0; j < NB_COLS; ++j) {
        float4 q = tile[j];
        float d = fmaf(x2, q.z, q.w);
        d = fmaf(x1, q.y, d);
        d = fmaf(x0, q.x, d);
        d += x2m;                                     // true sq distance >= 0
        unsigned int t = (__float_as_uint(d) & 0xFFFFF000u) | (nbase + j);
        #pragma unroll
        for (int s = 0; s < NB_K; ++s) {              // branchless sorted insert
            unsigned int lo = min(bd[s], t);
            t = max(bd[s], t);
            bd[s] = lo;
        }
    }
    #pragma unroll
    for (int k = 0; k < NB_K; ++k)
        g_nb[(chunk * NB_K + k) * TOT + m] = bd[k];
}

// kNN pass 2: merge 8 sorted top-9 key lists, drop self, emit idx + sd.
__global__ void __launch_bounds__(256) nb_merge_kernel() {
    int m = blockIdx.x * 256 + threadIdx.x;
    unsigned int bd[NB_K];
    #pragma unroll
    for (int k = 0; k < NB_K; ++k) bd[k] = g_nb[k * TOT + m];
    for (int c = 1; c < NB_CHUNKS; ++c) {
        #pragma unroll
        for (int k = 0; k < NB_K; ++k) {
            unsigned int t = g_nb[(c * NB_K + k) * TOT + m];
            if (t >= bd[NB_K - 1]) break;     // both lists sorted ascending
            #pragma unroll
            for (int s = 0; s < NB_K; ++s) {
                unsigned int lo = min(bd[s], t);
                t = max(bd[s], t);
                bd[s] = lo;
            }
        }
    }
    float4 me = g_cols_src[m];
    float x0 = -0.5f * me.x, x1 = -0.5f * me.y, x2 = -0.5f * me.z;
    int ml = m & (NN - 1);
    int mb = m & ~(NN - 1);                   // b*NN
    int cnt = 0;
    #pragma unroll
    for (int s = 0; s < NB_K; ++s) {
        int j = (int)(bd[s] & 0xFFFu);
        if (j != ml && cnt < KK) {
            float4 q = g_cols_src[mb + j];
            float d = fmaf(x2, q.z, q.w);
            d = fmaf(x1, q.y, d);
            d = fmaf(x0, q.x, d);
            d += me.w;
            g_idx[cnt * TOT + m] = j;
            g_sd[cnt * TOT + m]  = sqrtf(d + 1e-5f);
            cnt++;
        }
    }
}

// ---------------------------------------------------------------------------
// ARAP per t: gather dp neighbors (float4 LDG.128), compare to source dists.
__global__ void arap_kernel() {
    __shared__ float red[256];
    int t = blockIdx.y;
    int i = blockIdx.x * 256 + threadIdx.x;    // b*NN + n
    int b = i >> 12;
    const float4* dpb = g_dp4 + (size_t)(t * BB + b) * NN;
    float4 pme = dpb[i & (NN - 1)];
    float acc = 0.f;
    #pragma unroll
    for (int k = 0; k < KK; ++k) {
        int j = g_idx[k * TOT + i];
        float4 q = dpb[j];
        float dx = q.x - pme.x;
        float dy = q.y - pme.y;
        float dz = q.z - pme.z;
        float dd = sqrtf(fmaf(dx, dx, fmaf(dy, dy, dz * dz)) + 1e-5f);
        float df = dd - g_sd[k * TOT + i];
        acc = fmaf(df, df, acc);
    }
    float s = block_reduce_sum<256>(acc, red);
    if (threadIdx.x == 0) g_partial[P_ARAP + t * 64 + blockIdx.x] = s;
}

// ---------------------------------------------------------------------------
// Final deterministic weighted reduction of all partial slots.
__global__ void final_kernel(float* __restrict__ out) {
    __shared__ float red[256];
    int tid = threadIdx.x;
    float acc = 0.f;
    for (int s = tid; s < NPART; s += 256) {
        float w;
        if (s < P_PD)        w = 0.5f / BB;          // chamfer: *0.5/B
        else if (s < P_SP)   w = 1.0f / BB;          // pd: /B
        else if (s < P_TRAN) w = 1.0f / (BB * NN);   // sp: mean over B*N
        else                 w = 1.0f / BB;          // tran + arap: /B
        acc += w * g_partial[s];
    }
    float s = block_reduce_sum<256>(acc, red);
    if (tid == 0) out[0] = s;
}

// ---------------------------------------------------------------------------
extern "C" void kernel_launch(void* const* d_in, const int* in_sizes, int n_in,
                              void* d_out, int out_size) {
    (void)in_sizes; (void)n_in; (void)out_size;
    const float* pw  = (const float*)d_in[1];  // point_weight [T,B,N,1]
    const float* drp = (const float*)d_in[2];  // deform_rigid_points [T,B,N,3]
    const float* dpt = (const float*)d_in[3];  // deformation_points [T,B,N,3]
    const float* rig = (const float*)d_in[4];  // rigid_matrix [T,B,4,4]
    const float* src = (const float*)d_in[5];  // source_points [B,N,3]
    const float* tgt = (const float*)d_in[6];  // target_points [B,N,3]

    prep_kernel<<<192, 256>>>(src, tgt, dpt);
    small_kernel<<<64, 256>>>(pw, drp, dpt, rig);
    chamfer_kernel<<<dim3(8, 24 * CCH), 128>>>(dpt, tgt);
    nb_kernel<<<dim3(TOT / 256, NB_CHUNKS), 256>>>();      // 4th — ncu target
    nb_merge_kernel<<<TOT / 256, 256>>>();
    chamfer_combine<<<dim3(16, 24), 256>>>(dpt, tgt);
    arap_kernel<<<dim3(TOT / 256, TT), 256>>>();
    final_kernel<<<1, 256>>>((float*)d_out);
}

// round 11
// speedup vs baseline: 1.4524x; 1.0032x over previous
#include <cuda_runtime.h>
#include <math.h>

// Shapes fixed by the problem: T=3, B=4, N=4096, K=8.
constexpr int TT = 3;
constexpr int BB = 4;
constexpr int NN = 4096;
constexpr int KK = 8;
constexpr int TOT = BB * NN;               // 16384 rows
constexpr int NB_CHUNKS = 8;
constexpr int NB_COLS = NN / NB_CHUNKS;    // 512
constexpr int NB_K = 9;                    // top-9 (self dropped in merge)
constexpr int NPAIR = NN / 2;              // 2048 packed column pairs per set
constexpr int CCH = 4;                     // chamfer column chunks
constexpr int CPAIR = NPAIR / CCH;         // 512 pairs per chamfer chunk

// Partial-sum slot layout (deterministic reduction — no float atomics)
constexpr int P_CH   = 0;                  // 24 problems * 16 blocks = 384
constexpr int P_PD   = 384;                // 64
constexpr int P_SP   = 448;                // 64
constexpr int P_TRAN = 512;                // 1
constexpr int P_ARAP = 513;                // 3 * 64 = 192
constexpr int NPART  = 705;

// Scratch (device globals — no allocations allowed)
__device__ ulonglong2 g_tgtA[BB * NPAIR];      // (-2x pair, -2y pair) target
__device__ ulonglong2 g_tgtB[BB * NPAIR];      // (-2z pair, |p|^2 pair)
__device__ ulonglong2 g_dpA[TT * BB * NPAIR];  // same for deformation pts
__device__ ulonglong2 g_dpB[TT * BB * NPAIR];
__device__ float4 g_cols_src[TOT];             // (-2x,-2y,-2z,|x|^2) src (kNN)
__device__ float4 g_dp4[TT * TOT];             // raw dp coords (arap gathers)
__device__ unsigned int g_nb[NB_CHUNKS * NB_K * TOT];  // packed keys [chunk][k][m]
__device__ int    g_idx[KK * TOT];             // [k][m]
__device__ float  g_sd[KK * TOT];
__device__ float  g_cmin[24 * CCH * NN];       // chamfer partial row-mins
__device__ float  g_partial[NPART];

// ---------------------------------------------------------------------------
__device__ __forceinline__ unsigned long long packf2(float a, float b) {
    unsigned long long r;
    asm("mov.b64 %0, {%1, %2};" : "=l"(r) : "f"(a), "f"(b));
    return r;
}
__device__ __forceinline__ void unpackf2(float& a, float& b, unsigned long long v) {
    asm("mov.b64 {%0, %1}, %2;" : "=f"(a), "=f"(b) : "l"(v));
}
__device__ __forceinline__ unsigned long long fma2(unsigned long long a,
                                                   unsigned long long b,
                                                   unsigned long long c) {
    unsigned long long d;
    asm("fma.rn.f32x2 %0, %1, %2, %3;" : "=l"(d) : "l"(a), "l"(b), "l"(c));
    return d;
}

template <int BS>
__device__ __forceinline__ float block_reduce_sum(float v, float* sh) {
    int tid = threadIdx.x;
    sh[tid] = v;
    __syncthreads();
    #pragma unroll
    for (int s = BS / 2; s > 0; s >>= 1) {
        if (tid < s) sh[tid] += sh[tid + s];
        __syncthreads();
    }
    float r = sh[0];
    __syncthreads();
    return r;
}

// ---------------------------------------------------------------------------
// Build all derived layouts.
__global__ void prep_kernel(const float* __restrict__ src,
                            const float* __restrict__ tgt,
                            const float* __restrict__ dpt) {
    int i = blockIdx.x * 256 + threadIdx.x;   // 0 .. 49151
    if (i < BB * NPAIR) {                     // target pairs
        const float* p = tgt + (size_t)i * 6;
        float x0 = p[0], y0 = p[1], z0 = p[2];
        float x1 = p[3], y1 = p[4], z1 = p[5];
        float w0 = fmaf(x0, x0, fmaf(y0, y0, z0 * z0));
        float w1 = fmaf(x1, x1, fmaf(y1, y1, z1 * z1));
        g_tgtA[i] = make_ulonglong2(packf2(-2.f * x0, -2.f * x1),
                                    packf2(-2.f * y0, -2.f * y1));
        g_tgtB[i] = make_ulonglong2(packf2(-2.f * z0, -2.f * z1),
                                    packf2(w0, w1));
    } else if (i < (BB + TT * BB) * NPAIR) {  // dp pairs (+ raw dp4)
        int j = i - BB * NPAIR;
        const float* p = dpt + (size_t)j * 6;
        float x0 = p[0], y0 = p[1], z0 = p[2];
        float x1 = p[3], y1 = p[4], z1 = p[5];
        float w0 = fmaf(x0, x0, fmaf(y0, y0, z0 * z0));
        float w1 = fmaf(x1, x1, fmaf(y1, y1, z1 * z1));
        g_dpA[j] = make_ulonglong2(packf2(-2.f * x0, -2.f * x1),
                                   packf2(-2.f * y0, -2.f * y1));
        g_dpB[j] = make_ulonglong2(packf2(-2.f * z0, -2.f * z1),
                                   packf2(w0, w1));
        g_dp4[2 * j + 0] = make_float4(x0, y0, z0, 0.f);
        g_dp4[2 * j + 1] = make_float4(x1, y1, z1, 0.f);
    } else {                                  // source columns (kNN)
        int j = i - (BB + TT * BB) * NPAIR;
        if (j >= TOT) return;
        const float* p = src + (size_t)j * 3;
        float x = p[0], y = p[1], z = p[2];
        g_cols_src[j] = make_float4(-2.f * x, -2.f * y, -2.f * z,
                                    fmaf(x, x, fmaf(y, y, z * z)));
    }
}

// ---------------------------------------------------------------------------
// pd (sum sq diff), sp (sum abs), tran (tiny) — partial sums per block.
__global__ void small_kernel(const float* __restrict__ pw,
                             const float* __restrict__ drp,
                             const float* __restrict__ dpt,
                             const float* __restrict__ rig) {
    __shared__ float red[256];
    int g = blockIdx.x * 256 + threadIdx.x;
    float spa = 0.f, pda = 0.f;
    for (int i = g; i < TT * TOT; i += 64 * 256) {
        spa += fabsf(pw[i]);
        int b3 = i * 3;
        float a = drp[b3 + 0] - dpt[b3 + 0];
        float c = drp[b3 + 1] - dpt[b3 + 1];
        float e = drp[b3 + 2] - dpt[b3 + 2];
        pda += fmaf(a, a, fmaf(c, c, e * e));
    }
    float s1 = block_reduce_sum<256>(pda, red);
    if (threadIdx.x == 0) g_partial[P_PD + blockIdx.x] = s1;
    float s2 = block_reduce_sum<256>(spa, red);
    if (threadIdx.x == 0) g_partial[P_SP + blockIdx.x] = s2;

    float ta = 0.f;
    if (blockIdx.x == 0 && threadIdx.x < TT * BB * 3) {
        int t = threadIdx.x / 12;
        int rem = threadIdx.x % 12;
        int b = rem / 3, r = rem % 3;
        float v = rig[(((t * BB + b) * 4) + r) * 4 + 3];
        ta = v * v;
    }
    float s3 = block_reduce_sum<256>(ta, red);
    if (blockIdx.x == 0 && threadIdx.x == 0) g_partial[P_TRAN] = s3;
}

// ---------------------------------------------------------------------------
// Chamfer pass 1: 24 problems x 4 column chunks; 4-row register tiling +
// f32x2 packed columns; scalar FMNMX on unpacked halves (unpack = free
// register aliasing). Per 2 cols x 4 rows: 2 LDS.128 + 12 FFMA2 + 8 FMNMX.
__global__ void __launch_bounds__(128) chamfer_kernel(const float* __restrict__ dpt,
                                                      const float* __restrict__ tgt) {
    __shared__ ulonglong2 tA[CPAIR];   // 8KB — 1024 columns
    __shared__ ulonglong2 tB[CPAIR];   // 8KB
    int tid = threadIdx.x;
    int by = blockIdx.y;               // p*CCH + cc
    int p = by >> 2;                   // ((t*BB + b)*2 + dir)
    int cc = by & 3;
    int dir = p & 1;
    int tb = p >> 1;
    int b = tb & 3;

    const float* rowp;
    const ulonglong2 *cA, *cB;
    if (dir == 0) { rowp = dpt + (size_t)tb * NN * 3; cA = g_tgtA + b * NPAIR;  cB = g_tgtB + b * NPAIR; }
    else          { rowp = tgt + (size_t)b * NN * 3;  cA = g_dpA + tb * NPAIR;  cB = g_dpB + tb * NPAIR; }
    cA += cc * CPAIR;
    cB += cc * CPAIR;

    #pragma unroll
    for (int j = tid; j < CPAIR; j += 128) { tA[j] = cA[j]; tB[j] = cB[j]; }
    __syncthreads();

    int m0 = blockIdx.x * 512 + tid;   // rows m0, +128, +256, +384
    unsigned long long X0[4], X1[4], X2[4];
    float rlo[4], rhi[4];
    #pragma unroll
    for (int r = 0; r < 4; ++r) {
        const float* rp = rowp + (size_t)(m0 + r * 128) * 3;
        float a0 = rp[0], a1 = rp[1], a2 = rp[2];
        X0[r] = packf2(a0, a0); X1[r] = packf2(a1, a1); X2[r] = packf2(a2, a2);
        rlo[r] = 3.4e38f; rhi[r] = 3.4e38f;
    }

    #pragma unroll 4
    for (int j = 0; j < CPAIR; ++j) {
        ulonglong2 ca = tA[j];
        ulonglong2 cb = tB[j];
        #pragma unroll
        for (int r = 0; r < 4; ++r) {
            unsigned long long d = fma2(X2[r], cb.x, cb.y);
            d = fma2(X1[r], ca.y, d);
            d = fma2(X0[r], ca.x, d);
            float lo, hi;
            unpackf2(lo, hi, d);
            rlo[r] = fminf(rlo[r], lo);
            rhi[r] = fminf(rhi[r], hi);
        }
    }
    float* out = g_cmin + (size_t)by * NN;
    #pragma unroll
    for (int r = 0; r < 4; ++r)
        out[m0 + r * 128] = fminf(rlo[r], rhi[r]);
}

// Chamfer pass 2: combine 4 chunk mins + |x|^2, block-sum into partials.
__global__ void __launch_bounds__(256) chamfer_combine(const float* __restrict__ dpt,
                                                       const float* __restrict__ tgt) {
    __shared__ float red[256];
    int p = blockIdx.y;
    int dir = p & 1;
    int tb = p >> 1;
    int b = tb & 3;
    const float* rowp = (dir == 0) ? dpt + (size_t)tb * NN * 3
                                   : tgt + (size_t)b * NN * 3;
    int m = blockIdx.x * 256 + threadIdx.x;
    const float* cm = g_cmin + (size_t)p * CCH * NN + m;
    float v = fminf(fminf(cm[0], cm[NN]), fminf(cm[2 * NN], cm[3 * NN]));
    const float* rp = rowp + (size_t)m * 3;
    float x0 = rp[0], x1 = rp[1], x2 = rp[2];
    v += fmaf(x0, x0, fmaf(x1, x1, x2 * x2));
    float s = block_reduce_sum<256>(v, red);
    if (threadIdx.x == 0) g_partial[P_CH + p * 16 + blockIdx.x] = s;
}

// ---------------------------------------------------------------------------
// kNN pass 1: 8 column chunks of 512; one row per thread. Branchless
// packed-key top-9 ladder, MIXED PIPES: keys are positive-float bit patterns
// so uint order == float order. Per slot: min via IMNMX (alu pipe), max via
// FMNMX (fma pipe) — the possibly-denormal self key only ever travels the
// bit-exact uint-min path, so FTZ cannot corrupt its index bits. Sign mask
// 0x7FFFF000 folds a rounding-negative self distance to ~+0 (keeps the
// uint/float orderings consistent for every key).
__global__ void __launch_bounds__(256) nb_kernel() {
    __shared__ float4 tile[NB_COLS];          // 8KB
    int tid = threadIdx.x;
    int m = blockIdx.x * 256 + tid;           // 0 .. TOT-1
    int b = m >> 12;
    int chunk = blockIdx.y;

    const float4* cb = g_cols_src + b * NN + chunk * NB_COLS;
    #pragma unroll
    for (int j = tid; j < NB_COLS; j += 256) tile[j] = cb[j];
    __syncthreads();

    float4 me = g_cols_src[m];   // (-2x,-2y,-2z,|x|^2)
    float x0 = -0.5f * me.x, x1 = -0.5f * me.y, x2 = -0.5f * me.z;
    float x2m = me.w;

    unsigned int bd[NB_K];
    #pragma unroll
    for (int k = 0; k < NB_K; ++k) bd[k] = 0x7F800000u;   // +inf keys

    unsigned int nbase = chunk * NB_COLS;
    #pragma unroll 4
    for (int j = 0; j < NB_COLS; ++j) {
        float4 q = tile[j];
        float d = fmaf(x2, q.z, q.w);
        d = fmaf(x1, q.y, d);
        d = fmaf(x0, q.x, d);
        d += x2m;                                     // true sq distance >= ~0
        unsigned int t = (__float_as_uint(d) & 0x7FFFF000u) | (nbase + j);
        #pragma unroll
        for (int s = 0; s < NB_K; ++s) {              // branchless mixed ladder
            unsigned int lo = min(bd[s], t);                       // IMNMX (alu)
            unsigned int hi = __float_as_uint(
                fmaxf(__uint_as_float(bd[s]), __uint_as_float(t))); // FMNMX (fma)
            bd[s] = lo; t = hi;
        }
    }
    #pragma unroll
    for (int k = 0; k < NB_K; ++k)
        g_nb[(chunk * NB_K + k) * TOT + m] = bd[k];
}

// kNN pass 2: merge 8 sorted top-9 key lists (bit-exact uint ladder),
// drop self, emit idx + sd (distance recomputed exactly from idx).
__global__ void __launch_bounds__(256) nb_merge_kernel() {
    int m = blockIdx.x * 256 + threadIdx.x;
    unsigned int bd[NB_K];
    #pragma unroll
    for (int k = 0; k < NB_K; ++k) bd[k] = g_nb[k * TOT + m];
    for (int c = 1; c < NB_CHUNKS; ++c) {
        #pragma unroll
        for (int k = 0; k < NB_K; ++k) {
            unsigned int t = g_nb[(c * NB_K + k) * TOT + m];
            if (t >= bd[NB_K - 1]) break;     // both lists sorted ascending
            #pragma unroll
            for (int s = 0; s < NB_K; ++s) {
                unsigned int lo = min(bd[s], t);
                t = max(bd[s], t);
                bd[s] = lo;
            }
        }
    }
    float4 me = g_cols_src[m];
    float x0 = -0.5f * me.x, x1 = -0.5f * me.y, x2 = -0.5f * me.z;
    int ml = m & (NN - 1);
    int mb = m & ~(NN - 1);                   // b*NN
    int cnt = 0;
    #pragma unroll
    for (int s = 0; s < NB_K; ++s) {
        int j = (int)(bd[s] & 0xFFFu);
        if (j != ml && cnt < KK) {
            float4 q = g_cols_src[mb + j];
            float d = fmaf(x2, q.z, q.w);
            d = fmaf(x1, q.y, d);
            d = fmaf(x0, q.x, d);
            d += me.w;
            g_idx[cnt * TOT + m] = j;
            g_sd[cnt * TOT + m]  = sqrtf(d + 1e-5f);
            cnt++;
        }
    }
}

// ---------------------------------------------------------------------------
// ARAP per t: gather dp neighbors (float4 LDG.128), compare to source dists.
__global__ void arap_kernel() {
    __shared__ float red[256];
    int t = blockIdx.y;
    int i = blockIdx.x * 256 + threadIdx.x;    // b*NN + n
    int b = i >> 12;
    const float4* dpb = g_dp4 + (size_t)(t * BB + b) * NN;
    float4 pme = dpb[i & (NN - 1)];
    float acc = 0.f;
    #pragma unroll
    for (int k = 0; k < KK; ++k) {
        int j = g_idx[k * TOT + i];
        float4 q = dpb[j];
        float dx = q.x - pme.x;
        float dy = q.y - pme.y;
        float dz = q.z - pme.z;
        float dd = sqrtf(fmaf(dx, dx, fmaf(dy, dy, dz * dz)) + 1e-5f);
        float df = dd - g_sd[k * TOT + i];
        acc = fmaf(df, df, acc);
    }
    float s = block_reduce_sum<256>(acc, red);
    if (threadIdx.x == 0) g_partial[P_ARAP + t * 64 + blockIdx.x] = s;
}

// ---------------------------------------------------------------------------
// Final deterministic weighted reduction of all partial slots.
__global__ void final_kernel(float* __restrict__ out) {
    __shared__ float red[256];
    int tid = threadIdx.x;
    float acc = 0.f;
    for (int s = tid; s < NPART; s += 256) {
        float w;
        if (s < P_PD)        w = 0.5f / BB;          // chamfer: *0.5/B
        else if (s < P_SP)   w = 1.0f / BB;          // pd: /B
        else if (s < P_TRAN) w = 1.0f / (BB * NN);   // sp: mean over B*N
        else                 w = 1.0f / BB;          // tran + arap: /B
        acc += w * g_partial[s];
    }
    float s = block_reduce_sum<256>(acc, red);
    if (tid == 0) out[0] = s;
}

// ---------------------------------------------------------------------------
extern "C" void kernel_launch(void* const* d_in, const int* in_sizes, int n_in,
                              void* d_out, int out_size) {
    (void)in_sizes; (void)n_in; (void)out_size;
    const float* pw  = (const float*)d_in[1];  // point_weight [T,B,N,1]
    const float* drp = (const float*)d_in[2];  // deform_rigid_points [T,B,N,3]
    const float* dpt = (const float*)d_in[3];  // deformation_points [T,B,N,3]
    const float* rig = (const float*)d_in[4];  // rigid_matrix [T,B,4,4]
    const float* src = (const float*)d_in[5];  // source_points [B,N,3]
    const float* tgt = (const float*)d_in[6];  // target_points [B,N,3]

    prep_kernel<<<192, 256>>>(src, tgt, dpt);
    small_kernel<<<64, 256>>>(pw, drp, dpt, rig);
    chamfer_kernel<<<dim3(8, 24 * CCH), 128>>>(dpt, tgt);
    nb_kernel<<<dim3(TOT / 256, NB_CHUNKS), 256>>>();      // 4th — ncu target
    nb_merge_kernel<<<TOT / 256, 256>>>();
    chamfer_combine<<<dim3(16, 24), 256>>>(dpt, tgt);
    arap_kernel<<<dim3(TOT / 256, TT), 256>>>();
    final_kernel<<<1, 256>>>((float*)d_out);
}

// round 12
// speedup vs baseline: 1.7523x; 1.2065x over previous
#include <cuda_runtime.h>
#include <math.h>

// Shapes fixed by the problem: T=3, B=4, N=4096, K=8.
constexpr int TT = 3;
constexpr int BB = 4;
constexpr int NN = 4096;
constexpr int KK = 8;
constexpr int TOT = BB * NN;               // 16384 rows
constexpr int NB_CHUNKS = 8;
constexpr int NB_COLS = NN / NB_CHUNKS;    // 512
constexpr int NB_K = 9;                    // top-9 (self dropped in merge)
constexpr int NPAIR = NN / 2;              // 2048 packed column pairs per set
constexpr int CCH = 4;                     // chamfer column chunks
constexpr int CPAIR = NPAIR / CCH;         // 512 pairs per chamfer chunk
constexpr int CH_BLOCKS = 24 * CCH * 4;    // 384 chamfer blocks (96 jobs x 4)
constexpr int NB_BLOCKS = (TOT / 256) * NB_CHUNKS;  // 512 nb blocks
constexpr int FUSED_BLOCKS = CH_BLOCKS + NB_BLOCKS; // 896 = 128 * 7

// Partial-sum slot layout (deterministic reduction — no float atomics)
constexpr int P_CH   = 0;                  // 24 problems * 16 blocks = 384
constexpr int P_PD   = 384;                // 64
constexpr int P_SP   = 448;                // 64
constexpr int P_TRAN = 512;                // 1
constexpr int P_ARAP = 513;                // 3 * 64 = 192
constexpr int NPART  = 705;

// Scratch (device globals — no allocations allowed)
__device__ ulonglong2 g_tgtA[BB * NPAIR];      // (-2x pair, -2y pair) target
__device__ ulonglong2 g_tgtB[BB * NPAIR];      // (-2z pair, |p|^2 pair)
__device__ ulonglong2 g_dpA[TT * BB * NPAIR];  // same for deformation pts
__device__ ulonglong2 g_dpB[TT * BB * NPAIR];
__device__ float4 g_cols_src[TOT];             // (-2x,-2y,-2z,|x|^2) src (kNN)
__device__ float4 g_dp4[TT * TOT];             // raw dp coords (arap gathers)
__device__ unsigned int g_nb[NB_CHUNKS * NB_K * TOT];  // packed keys [chunk][k][m]
__device__ int    g_idx[KK * TOT];             // [k][m]
__device__ float  g_sd[KK * TOT];
__device__ float  g_cmin[24 * CCH * NN];       // chamfer partial row-mins
__device__ float  g_partial[NPART];

// ---------------------------------------------------------------------------
__device__ __forceinline__ unsigned long long packf2(float a, float b) {
    unsigned long long r;
    asm("mov.b64 %0, {%1, %2};" : "=l"(r) : "f"(a), "f"(b));
    return r;
}
__device__ __forceinline__ void unpackf2(float& a, float& b, unsigned long long v) {
    asm("mov.b64 {%0, %1}, %2;" : "=f"(a), "=f"(b) : "l"(v));
}
__device__ __forceinline__ unsigned long long fma2(unsigned long long a,
                                                   unsigned long long b,
                                                   unsigned long long c) {
    unsigned long long d;
    asm("fma.rn.f32x2 %0, %1, %2, %3;" : "=l"(d) : "l"(a), "l"(b), "l"(c));
    return d;
}

template <int BS>
__device__ __forceinline__ float block_reduce_sum(float v, float* sh) {
    int tid = threadIdx.x;
    sh[tid] = v;
    __syncthreads();
    #pragma unroll
    for (int s = BS / 2; s > 0; s >>= 1) {
        if (tid < s) sh[tid] += sh[tid + s];
        __syncthreads();
    }
    float r = sh[0];
    __syncthreads();
    return r;
}

// ---------------------------------------------------------------------------
// prepA: packed f32x2 chamfer columns for target + dp, and raw dp4 coords.
__global__ void prepA_kernel(const float* __restrict__ tgt,
                             const float* __restrict__ dpt) {
    int i = blockIdx.x * 256 + threadIdx.x;   // 0 .. 32767
    if (i < BB * NPAIR) {                     // target pairs
        const float* p = tgt + (size_t)i * 6;
        float x0 = p[0], y0 = p[1], z0 = p[2];
        float x1 = p[3], y1 = p[4], z1 = p[5];
        float w0 = fmaf(x0, x0, fmaf(y0, y0, z0 * z0));
        float w1 = fmaf(x1, x1, fmaf(y1, y1, z1 * z1));
        g_tgtA[i] = make_ulonglong2(packf2(-2.f * x0, -2.f * x1),
                                    packf2(-2.f * y0, -2.f * y1));
        g_tgtB[i] = make_ulonglong2(packf2(-2.f * z0, -2.f * z1),
                                    packf2(w0, w1));
    } else {                                  // dp pairs (+ raw dp4)
        int j = i - BB * NPAIR;
        if (j >= TT * BB * NPAIR) return;
        const float* p = dpt + (size_t)j * 6;
        float x0 = p[0], y0 = p[1], z0 = p[2];
        float x1 = p[3], y1 = p[4], z1 = p[5];
        float w0 = fmaf(x0, x0, fmaf(y0, y0, z0 * z0));
        float w1 = fmaf(x1, x1, fmaf(y1, y1, z1 * z1));
        g_dpA[j] = make_ulonglong2(packf2(-2.f * x0, -2.f * x1),
                                   packf2(-2.f * y0, -2.f * y1));
        g_dpB[j] = make_ulonglong2(packf2(-2.f * z0, -2.f * z1),
                                   packf2(w0, w1));
        g_dp4[2 * j + 0] = make_float4(x0, y0, z0, 0.f);
        g_dp4[2 * j + 1] = make_float4(x1, y1, z1, 0.f);
    }
}

// prepB: kNN source column array.
__global__ void prepB_kernel(const float* __restrict__ src) {
    int j = blockIdx.x * 256 + threadIdx.x;   // 0 .. 16383
    const float* p = src + (size_t)j * 3;
    float x = p[0], y = p[1], z = p[2];
    g_cols_src[j] = make_float4(-2.f * x, -2.f * y, -2.f * z,
                                fmaf(x, x, fmaf(y, y, z * z)));
}

// ---------------------------------------------------------------------------
// pd (sum sq diff), sp (sum abs), tran (tiny) — partial sums per block.
__global__ void small_kernel(const float* __restrict__ pw,
                             const float* __restrict__ drp,
                             const float* __restrict__ dpt,
                             const float* __restrict__ rig) {
    __shared__ float red[256];
    int g = blockIdx.x * 256 + threadIdx.x;
    float spa = 0.f, pda = 0.f;
    for (int i = g; i < TT * TOT; i += 64 * 256) {
        spa += fabsf(pw[i]);
        int b3 = i * 3;
        float a = drp[b3 + 0] - dpt[b3 + 0];
        float c = drp[b3 + 1] - dpt[b3 + 1];
        float e = drp[b3 + 2] - dpt[b3 + 2];
        pda += fmaf(a, a, fmaf(c, c, e * e));
    }
    float s1 = block_reduce_sum<256>(pda, red);
    if (threadIdx.x == 0) g_partial[P_PD + blockIdx.x] = s1;
    float s2 = block_reduce_sum<256>(spa, red);
    if (threadIdx.x == 0) g_partial[P_SP + blockIdx.x] = s2;

    float ta = 0.f;
    if (blockIdx.x == 0 && threadIdx.x < TT * BB * 3) {
        int t = threadIdx.x / 12;
        int rem = threadIdx.x % 12;
        int b = rem / 3, r = rem % 3;
        float v = rig[(((t * BB + b) * 4) + r) * 4 + 3];
        ta = v * v;
    }
    float s3 = block_reduce_sum<256>(ta, red);
    if (blockIdx.x == 0 && threadIdx.x == 0) g_partial[P_TRAN] = s3;
}

// ---------------------------------------------------------------------------
// FUSED kernel: chamfer blocks (fma-pipe heavy) + kNN blocks (alu-pipe heavy)
// interleaved 3:4 per group of 7 so both types co-reside per SM and the two
// pipes overlap instead of running serially.
union FusedSmem {
    struct { ulonglong2 tA[CPAIR]; ulonglong2 tB[CPAIR]; } ch;  // 16KB
    float4 nb_tile[NB_COLS];                                    // 8KB
};

__global__ void __launch_bounds__(256) fused_kernel(const float* __restrict__ dpt,
                                                    const float* __restrict__ tgt) {
    __shared__ FusedSmem sm;
    int tid = threadIdx.x;
    int grp = blockIdx.x / 7;
    int lane7 = blockIdx.x % 7;

    if (lane7 < 3) {
        // ----- chamfer part: cid in [0, 384) -----
        int cid = grp * 3 + lane7;
        int by = cid >> 2;             // 0..95 = p*CCH + cc
        int bx = cid & 3;
        int p = by >> 2;               // ((t*BB + b)*2 + dir)
        int cc = by & 3;
        int dir = p & 1;
        int tb = p >> 1;
        int b = tb & 3;

        const float* rowp;
        const ulonglong2 *cA, *cB;
        if (dir == 0) { rowp = dpt + (size_t)tb * NN * 3; cA = g_tgtA + b * NPAIR;  cB = g_tgtB + b * NPAIR; }
        else          { rowp = tgt + (size_t)b * NN * 3;  cA = g_dpA + tb * NPAIR;  cB = g_dpB + tb * NPAIR; }
        cA += cc * CPAIR;
        cB += cc * CPAIR;

        #pragma unroll
        for (int j = tid; j < CPAIR; j += 256) { sm.ch.tA[j] = cA[j]; sm.ch.tB[j] = cB[j]; }
        __syncthreads();

        int m0 = bx * 1024 + tid;      // rows m0, +256, +512, +768
        unsigned long long X0[4], X1[4], X2[4];
        float rlo[4], rhi[4];
        #pragma unroll
        for (int r = 0; r < 4; ++r) {
            const float* rp = rowp + (size_t)(m0 + r * 256) * 3;
            float a0 = rp[0], a1 = rp[1], a2 = rp[2];
            X0[r] = packf2(a0, a0); X1[r] = packf2(a1, a1); X2[r] = packf2(a2, a2);
            rlo[r] = 3.4e38f; rhi[r] = 3.4e38f;
        }

        #pragma unroll 4
        for (int j = 0; j < CPAIR; ++j) {
            ulonglong2 ca = sm.ch.tA[j];
            ulonglong2 cb = sm.ch.tB[j];
            #pragma unroll
            for (int r = 0; r < 4; ++r) {
                unsigned long long d = fma2(X2[r], cb.x, cb.y);
                d = fma2(X1[r], ca.y, d);
                d = fma2(X0[r], ca.x, d);
                float lo, hi;
                unpackf2(lo, hi, d);
                rlo[r] = fminf(rlo[r], lo);
                rhi[r] = fminf(rhi[r], hi);
            }
        }
        float* out = g_cmin + (size_t)by * NN;
        #pragma unroll
        for (int r = 0; r < 4; ++r)
            out[m0 + r * 256] = fminf(rlo[r], rhi[r]);
    } else {
        // ----- kNN part: nid in [0, 512) -----
        int nid = grp * 4 + (lane7 - 3);
        int chunk = nid & 7;
        int rb = nid >> 3;
        int m = rb * 256 + tid;        // 0 .. TOT-1
        int b = m >> 12;

        const float4* cb = g_cols_src + b * NN + chunk * NB_COLS;
        #pragma unroll
        for (int j = tid; j < NB_COLS; j += 256) sm.nb_tile[j] = cb[j];
        __syncthreads();

        float4 me = g_cols_src[m];     // (-2x,-2y,-2z,|x|^2)
        float x0 = -0.5f * me.x, x1 = -0.5f * me.y, x2 = -0.5f * me.z;
        float x2m = me.w;

        unsigned int bd[NB_K];
        #pragma unroll
        for (int k = 0; k < NB_K; ++k) bd[k] = 0x7F800000u;   // +inf keys

        unsigned int nbase = chunk * NB_COLS;
        // 2-column DPX merge: sort the pair (lo<=hi), then merge into the
        // sorted top-9 via r[s] = vimin3(bd[s], max(bd[s-1],lo), max(bd[s-2],hi)),
        // evaluated descending so old values are consumed before overwrite.
        #pragma unroll 2
        for (int j = 0; j < NB_COLS; j += 2) {
            float4 q0 = sm.nb_tile[j];
            float4 q1 = sm.nb_tile[j + 1];
            float d0 = fmaf(x2, q0.z, q0.w);
            float d1 = fmaf(x2, q1.z, q1.w);
            d0 = fmaf(x1, q0.y, d0);
            d1 = fmaf(x1, q1.y, d1);
            d0 = fmaf(x0, q0.x, d0);
            d1 = fmaf(x0, q1.x, d1);
            d0 += x2m;                                    // true sq dist >= ~0
            d1 += x2m;
            unsigned int t0 = (__float_as_uint(d0) & 0x7FFFF000u) | (nbase + j);
            unsigned int t1 = (__float_as_uint(d1) & 0x7FFFF000u) | (nbase + j + 1);
            unsigned int lo = min(t0, t1);
            unsigned int hi = max(t0, t1);
            #pragma unroll
            for (int s = NB_K - 1; s >= 2; --s)
                bd[s] = __vimin3_u32(bd[s], max(bd[s - 1], lo), max(bd[s - 2], hi));
            bd[1] = __vimin3_u32(bd[1], max(bd[0], lo), hi);
            bd[0] = min(bd[0], lo);
        }
        #pragma unroll
        for (int k = 0; k < NB_K; ++k)
            g_nb[(chunk * NB_K + k) * TOT + m] = bd[k];
    }
}

// ---------------------------------------------------------------------------
// Chamfer pass 2: combine 4 chunk mins + |x|^2, block-sum into partials.
__global__ void __launch_bounds__(256) chamfer_combine(const float* __restrict__ dpt,
                                                       const float* __restrict__ tgt) {
    __shared__ float red[256];
    int p = blockIdx.y;
    int dir = p & 1;
    int tb = p >> 1;
    int b = tb & 3;
    const float* rowp = (dir == 0) ? dpt + (size_t)tb * NN * 3
                                   : tgt + (size_t)b * NN * 3;
    int m = blockIdx.x * 256 + threadIdx.x;
    const float* cm = g_cmin + (size_t)p * CCH * NN + m;
    float v = fminf(fminf(cm[0], cm[NN]), fminf(cm[2 * NN], cm[3 * NN]));
    const float* rp = rowp + (size_t)m * 3;
    float x0 = rp[0], x1 = rp[1], x2 = rp[2];
    v += fmaf(x0, x0, fmaf(x1, x1, x2 * x2));
    float s = block_reduce_sum<256>(v, red);
    if (threadIdx.x == 0) g_partial[P_CH + p * 16 + blockIdx.x] = s;
}

// ---------------------------------------------------------------------------
// kNN pass 2: merge 8 sorted top-9 key lists (bit-exact uint ladder),
// drop self, emit idx + sd (distance recomputed exactly from idx).
__global__ void __launch_bounds__(256) nb_merge_kernel() {
    int m = blockIdx.x * 256 + threadIdx.x;
    unsigned int bd[NB_K];
    #pragma unroll
    for (int k = 0; k < NB_K; ++k) bd[k] = g_nb[k * TOT + m];
    for (int c = 1; c < NB_CHUNKS; ++c) {
        #pragma unroll
        for (int k = 0; k < NB_K; ++k) {
            unsigned int t = g_nb[(c * NB_K + k) * TOT + m];
            if (t >= bd[NB_K - 1]) break;     // both lists sorted ascending
            #pragma unroll
            for (int s = 0; s < NB_K; ++s) {
                unsigned int lo = min(bd[s], t);
                t = max(bd[s], t);
                bd[s] = lo;
            }
        }
    }
    float4 me = g_cols_src[m];
    float x0 = -0.5f * me.x, x1 = -0.5f * me.y, x2 = -0.5f * me.z;
    int ml = m & (NN - 1);
    int mb = m & ~(NN - 1);                   // b*NN
    int cnt = 0;
    #pragma unroll
    for (int s = 0; s < NB_K; ++s) {
        int j = (int)(bd[s] & 0xFFFu);
        if (j != ml && cnt < KK) {
            float4 q = g_cols_src[mb + j];
            float d = fmaf(x2, q.z, q.w);
            d = fmaf(x1, q.y, d);
            d = fmaf(x0, q.x, d);
            d += me.w;
            g_idx[cnt * TOT + m] = j;
            g_sd[cnt * TOT + m]  = sqrtf(d + 1e-5f);
            cnt++;
        }
    }
}

// ---------------------------------------------------------------------------
// ARAP per t: gather dp neighbors (float4 LDG.128), compare to source dists.
__global__ void arap_kernel() {
    __shared__ float red[256];
    int t = blockIdx.y;
    int i = blockIdx.x * 256 + threadIdx.x;    // b*NN + n
    int b = i >> 12;
    const float4* dpb = g_dp4 + (size_t)(t * BB + b) * NN;
    float4 pme = dpb[i & (NN - 1)];
    float acc = 0.f;
    #pragma unroll
    for (int k = 0; k < KK; ++k) {
        int j = g_idx[k * TOT + i];
        float4 q = dpb[j];
        float dx = q.x - pme.x;
        float dy = q.y - pme.y;
        float dz = q.z - pme.z;
        float dd = sqrtf(fmaf(dx, dx, fmaf(dy, dy, dz * dz)) + 1e-5f);
        float df = dd - g_sd[k * TOT + i];
        acc = fmaf(df, df, acc);
    }
    float s = block_reduce_sum<256>(acc, red);
    if (threadIdx.x == 0) g_partial[P_ARAP + t * 64 + blockIdx.x] = s;
}

// ---------------------------------------------------------------------------
// Final deterministic weighted reduction of all partial slots.
__global__ void final_kernel(float* __restrict__ out) {
    __shared__ float red[256];
    int tid = threadIdx.x;
    float acc = 0.f;
    for (int s = tid; s < NPART; s += 256) {
        float w;
        if (s < P_PD)        w = 0.5f / BB;          // chamfer: *0.5/B
        else if (s < P_SP)   w = 1.0f / BB;          // pd: /B
        else if (s < P_TRAN) w = 1.0f / (BB * NN);   // sp: mean over B*N
        else                 w = 1.0f / BB;          // tran + arap: /B
        acc += w * g_partial[s];
    }
    float s = block_reduce_sum<256>(acc, red);
    if (tid == 0) out[0] = s;
}

// ---------------------------------------------------------------------------
extern "C" void kernel_launch(void* const* d_in, const int* in_sizes, int n_in,
                              void* d_out, int out_size) {
    (void)in_sizes; (void)n_in; (void)out_size;
    const float* pw  = (const float*)d_in[1];  // point_weight [T,B,N,1]
    const float* drp = (const float*)d_in[2];  // deform_rigid_points [T,B,N,3]
    const float* dpt = (const float*)d_in[3];  // deformation_points [T,B,N,3]
    const float* rig = (const float*)d_in[4];  // rigid_matrix [T,B,4,4]
    const float* src = (const float*)d_in[5];  // source_points [B,N,3]
    const float* tgt = (const float*)d_in[6];  // target_points [B,N,3]

    prepA_kernel<<<128, 256>>>(tgt, dpt);
    prepB_kernel<<<64, 256>>>(src);
    small_kernel<<<64, 256>>>(pw, drp, dpt, rig);
    fused_kernel<<<FUSED_BLOCKS, 256>>>(dpt, tgt);   // launch index 3 — ncu target
    nb_merge_kernel<<<TOT / 256, 256>>>();
    chamfer_combine<<<dim3(16, 24), 256>>>(dpt, tgt);
    arap_kernel<<<dim3(TOT / 256, TT), 256>>>();
    final_kernel<<<1, 256>>>((float*)d_out);
}